// round 5
// baseline (speedup 1.0000x reference)
#include <cuda_runtime.h>
#include <cuda_fp16.h>
#include <cstdint>

#define DEVINL __device__ __forceinline__

static constexpr int B_ROWS = 131072;
static constexpr int DIM    = 256;
static constexpr int C_COLS = 1000;
static constexpr int C_PAD  = 1024;

// GEMM tiling
static constexpr int TILE_M  = 128;
static constexpr int TILE_N  = 256;
static constexpr int K_CHUNK = 64;                    // fp16 -> 128B smem rows
static constexpr int N_CHUNKS = DIM / K_CHUNK;        // 4
static constexpr int STAGE_A = TILE_M * K_CHUNK * 2;  // 16384
static constexpr int STAGE_B = TILE_N * K_CHUNK * 2;  // 32768
static constexpr int STAGE_BYTES = STAGE_A + STAGE_B; // 49152
static constexpr int SMEM_REQ = N_CHUNKS * STAGE_BYTES; // 196608

// scratch
__device__ __half g_xh[(size_t)B_ROWS * DIM];
__device__ __half g_wh[(size_t)C_PAD * DIM];
__device__ float  g_rx[B_ROWS];
__device__ float  g_sw[C_PAD];

// ---------------- helpers ----------------
DEVINL uint32_t smem_u32(const void* p) {
    uint32_t a;
    asm("{ .reg .u64 t; cvta.to.shared.u64 t, %1; cvt.u32.u64 %0, t; }" : "=r"(a) : "l"(p));
    return a;
}
DEVINL void cp16(uint32_t dst, const void* src) {
    asm volatile("cp.async.cg.shared.global [%0], [%1], 16;" :: "r"(dst), "l"(src));
}
DEVINL void cp_commit() { asm volatile("cp.async.commit_group;" ::: "memory"); }
template <int N> DEVINL void cp_wait() {
    asm volatile("cp.async.wait_group %0;" :: "n"(N) : "memory");
}
DEVINL uint32_t sw128(uint32_t off) { return off ^ ((off >> 3) & 0x70); }

#define LDSM_X4(r0, r1, r2, r3, addr)                                             \
    asm volatile("ldmatrix.sync.aligned.m8n8.x4.shared.b16 {%0,%1,%2,%3}, [%4];"  \
                 : "=r"(r0), "=r"(r1), "=r"(r2), "=r"(r3) : "r"(addr))

DEVINL void mma16816(float* d, const uint32_t* a, const uint32_t* b) {
    asm volatile(
        "mma.sync.aligned.m16n8k16.row.col.f32.f16.f16.f32 "
        "{%0,%1,%2,%3}, {%4,%5,%6,%7}, {%8,%9}, {%0,%1,%2,%3};"
        : "+f"(d[0]), "+f"(d[1]), "+f"(d[2]), "+f"(d[3])
        : "r"(a[0]), "r"(a[1]), "r"(a[2]), "r"(a[3]), "r"(b[0]), "r"(b[1]));
}

// ---------------- prep: fp32 -> fp16 + inverse row L2 norm ----------------
__global__ void prep_kernel(const float* __restrict__ src, __half* __restrict__ dsth,
                            float* __restrict__ dstn, int nrows, int valid) {
    int row  = (blockIdx.x * blockDim.x + threadIdx.x) >> 5;
    int lane = threadIdx.x & 31;
    if (row >= nrows) return;
    uint2* drow = reinterpret_cast<uint2*>(dsth + (size_t)row * DIM);
    if (row < valid) {
        const float4* p = reinterpret_cast<const float4*>(src + (size_t)row * DIM);
        float4 v0 = p[lane];
        float4 v1 = p[lane + 32];
        float s = v0.x * v0.x + v0.y * v0.y + v0.z * v0.z + v0.w * v0.w
                + v1.x * v1.x + v1.y * v1.y + v1.z * v1.z + v1.w * v1.w;
#pragma unroll
        for (int o = 16; o; o >>= 1) s += __shfl_xor_sync(0xFFFFFFFFu, s, o);
        __half2 h0 = __floats2half2_rn(v0.x, v0.y);
        __half2 h1 = __floats2half2_rn(v0.z, v0.w);
        __half2 h2 = __floats2half2_rn(v1.x, v1.y);
        __half2 h3 = __floats2half2_rn(v1.z, v1.w);
        uint2 u0, u1;
        u0.x = *reinterpret_cast<uint32_t*>(&h0);
        u0.y = *reinterpret_cast<uint32_t*>(&h1);
        u1.x = *reinterpret_cast<uint32_t*>(&h2);
        u1.y = *reinterpret_cast<uint32_t*>(&h3);
        drow[lane]      = u0;   // elems lane*4 .. +3
        drow[lane + 32] = u1;   // elems 128 + lane*4 .. +3
        if (lane == 0) dstn[row] = rsqrtf(s);
    } else {
        uint2 z = {0u, 0u};
        drow[lane]      = z;
        drow[lane + 32] = z;
        if (lane == 0) dstn[row] = 0.0f;
    }
}

// ---------------- GEMM ----------------
__global__ __launch_bounds__(256, 1)
void gemm_kernel(float* __restrict__ out) {
    extern __shared__ char smem[];
    uint32_t s0 = smem_u32(smem);

    int tid  = threadIdx.x;
    int wid  = tid >> 5;
    int lane = tid & 31;
    int bid  = blockIdx.x;
    int m0 = (bid >> 2) * TILE_M;
    int n0 = (bid & 3) * TILE_N;

    // issue all 4 stages (full K prefetch)
#pragma unroll
    for (int st = 0; st < N_CHUNKS; st++) {
        int k0 = st * K_CHUNK;
        uint32_t sA = s0 + st * STAGE_BYTES;
        uint32_t sB = sA + STAGE_A;
        const __half* xa = g_xh + (size_t)m0 * DIM + k0;
        const __half* wb = g_wh + (size_t)n0 * DIM + k0;
#pragma unroll
        for (int i = 0; i < 4; i++) {                 // A: 128 rows x 8 chunks
            int g = tid + i * 256;
            int row = g >> 3, c = g & 7;
            cp16(sA + sw128((uint32_t)(row * 128 + c * 16)), xa + row * DIM + c * 8);
        }
#pragma unroll
        for (int i = 0; i < 8; i++) {                 // B: 256 rows x 8 chunks
            int g = tid + i * 256;
            int row = g >> 3, c = g & 7;
            cp16(sB + sw128((uint32_t)(row * 128 + c * 16)), wb + row * DIM + c * 8);
        }
        cp_commit();
    }

    float acc[4][8][4];
#pragma unroll
    for (int i = 0; i < 4; i++)
#pragma unroll
        for (int j = 0; j < 8; j++)
#pragma unroll
            for (int k = 0; k < 4; k++) acc[i][j][k] = 0.0f;

    // 8 warps as 2(M) x 4(N): warp tile 64 x 64
    int warp_m = wid >> 2;       // 0..1
    int warp_n = wid & 3;        // 0..3

    int a_row  = warp_m * 64 + (lane & 15);
    int a_kadd = (lane & 16) >> 1;               // 0 or 8
    int b_row  = warp_n * 64 + (lane & 7) + ((lane & 16) >> 1);
    int b_kadd = lane & 8;                       // 0 or 8

#pragma unroll
    for (int c = 0; c < N_CHUNKS; c++) {
        if (c == 0) cp_wait<3>();
        else if (c == 1) cp_wait<2>();
        else if (c == 2) cp_wait<1>();
        else cp_wait<0>();
        __syncthreads();

        uint32_t sA = s0 + c * STAGE_BYTES;
        uint32_t sB = sA + STAGE_A;
#pragma unroll
        for (int ks = 0; ks < 4; ks++) {
            uint32_t a[4][4];
#pragma unroll
            for (int bm = 0; bm < 4; bm++) {
                int row  = a_row + bm * 16;
                int kcol = ks * 16 + a_kadd;
                LDSM_X4(a[bm][0], a[bm][1], a[bm][2], a[bm][3],
                        sA + sw128((uint32_t)(row * 128 + kcol * 2)));
            }
            uint32_t b[4][4];
#pragma unroll
            for (int bb = 0; bb < 4; bb++) {
                int row  = b_row + bb * 16;
                int kcol = ks * 16 + b_kadd;
                LDSM_X4(b[bb][0], b[bb][1], b[bb][2], b[bb][3],
                        sB + sw128((uint32_t)(row * 128 + kcol * 2)));
            }
#pragma unroll
            for (int bm = 0; bm < 4; bm++)
#pragma unroll
                for (int bb = 0; bb < 4; bb++) {
                    mma16816(acc[bm][2 * bb],     a[bm], &b[bb][0]);
                    mma16816(acc[bm][2 * bb + 1], a[bm], &b[bb][2]);
                }
        }
    }

    // ---------------- epilogue ----------------
#pragma unroll
    for (int bm = 0; bm < 4; bm++) {
        int ma = m0 + warp_m * 64 + bm * 16 + (lane >> 2);
        int mb = ma + 8;
        float ra = 2.0f * g_rx[ma];
        float rb = 2.0f * g_rx[mb];
        float* rowa = out + (size_t)ma * C_COLS;
        float* rowb = out + (size_t)mb * C_COLS;
#pragma unroll
        for (int bn = 0; bn < 8; bn++) {
            int col = n0 + warp_n * 64 + bn * 8 + (lane & 3) * 2;
            if (col < C_COLS) {
                float sc0 = g_sw[col];
                float sc1 = g_sw[col + 1];
                float2 va, vb;
                va.x = fminf(fmaf(ra * sc0, acc[bm][bn][0], -2.0f), 0.0f);
                va.y = fminf(fmaf(ra * sc1, acc[bm][bn][1], -2.0f), 0.0f);
                vb.x = fminf(fmaf(rb * sc0, acc[bm][bn][2], -2.0f), 0.0f);
                vb.y = fminf(fmaf(rb * sc1, acc[bm][bn][3], -2.0f), 0.0f);
                *reinterpret_cast<float2*>(rowa + col) = va;
                *reinterpret_cast<float2*>(rowb + col) = vb;
            }
        }
    }
}

// ---------------- launch ----------------
extern "C" void kernel_launch(void* const* d_in, const int* in_sizes, int n_in,
                              void* d_out, int out_size) {
    const float* x = (const float*)d_in[0];
    const float* w = (const float*)d_in[1];
    float* out = (float*)d_out;

    __half* xh = nullptr;  __half* wh = nullptr;
    float* rx = nullptr;   float* sw = nullptr;
    cudaGetSymbolAddress((void**)&xh, g_xh);
    cudaGetSymbolAddress((void**)&wh, g_wh);
    cudaGetSymbolAddress((void**)&rx, g_rx);
    cudaGetSymbolAddress((void**)&sw, g_sw);

    cudaFuncSetAttribute(gemm_kernel, cudaFuncAttributeMaxDynamicSharedMemorySize, SMEM_REQ);

    // prep: w (padded to 1024 rows) + x
    prep_kernel<<<C_PAD / 8, 256>>>(w, wh, sw, C_PAD, C_COLS);
    prep_kernel<<<B_ROWS / 8, 256>>>(x, xh, rx, B_ROWS, B_ROWS);

    // GEMM: 1024 m-tiles x 4 n-tiles; n fastest for x L2 reuse
    gemm_kernel<<<(B_ROWS / TILE_M) * 4, 256, SMEM_REQ>>>(out);

    // weight passthrough (second output)
    long long logits_elems = (long long)B_ROWS * C_COLS;
    if ((long long)out_size >= logits_elems + (long long)C_COLS * DIM) {
        cudaMemcpyAsync(out + logits_elems, w, (size_t)C_COLS * DIM * sizeof(float),
                        cudaMemcpyDeviceToDevice);
    }
}

// round 9
// speedup vs baseline: 1.2716x; 1.2716x over previous
#include <cuda_runtime.h>
#include <cuda_fp16.h>
#include <cstdint>

#define DEVINL __device__ __forceinline__

static constexpr int B_ROWS = 131072;
static constexpr int DIM    = 256;
static constexpr int C_COLS = 1000;
static constexpr int C_PAD  = 1024;

// GEMM tiling: CTA 128x128, 8 warps as 2(M) x 4(N) -> warp tile 64x32
static constexpr int TILE_M  = 128;
static constexpr int TILE_N  = 128;
static constexpr int K_CHUNK = 64;                     // fp16 -> 128B smem rows
static constexpr int N_CHUNKS = DIM / K_CHUNK;         // 4
static constexpr int N_STAGES = 3;
static constexpr int STAGE_A = TILE_M * K_CHUNK * 2;   // 16384
static constexpr int STAGE_B = TILE_N * K_CHUNK * 2;   // 16384
static constexpr int STAGE_BYTES = STAGE_A + STAGE_B;  // 32768
static constexpr int SMEM_REQ = N_STAGES * STAGE_BYTES; // 98304 -> 2 CTAs/SM

// scratch
__device__ __half g_xh[(size_t)B_ROWS * DIM];
__device__ __half g_wh[(size_t)C_PAD * DIM];
__device__ float  g_rx[B_ROWS];
__device__ float  g_sw[C_PAD];

// ---------------- helpers ----------------
DEVINL uint32_t smem_u32(const void* p) {
    uint32_t a;
    asm("{ .reg .u64 t; cvta.to.shared.u64 t, %1; cvt.u32.u64 %0, t; }" : "=r"(a) : "l"(p));
    return a;
}
DEVINL void cp16(uint32_t dst, const void* src) {
    asm volatile("cp.async.cg.shared.global [%0], [%1], 16;" :: "r"(dst), "l"(src));
}
DEVINL void cp_commit() { asm volatile("cp.async.commit_group;" ::: "memory"); }
template <int N> DEVINL void cp_wait() {
    asm volatile("cp.async.wait_group %0;" :: "n"(N) : "memory");
}
DEVINL uint32_t sw128(uint32_t off) { return off ^ ((off >> 3) & 0x70); }

#define LDSM_X4(r0, r1, r2, r3, addr)                                             \
    asm volatile("ldmatrix.sync.aligned.m8n8.x4.shared.b16 {%0,%1,%2,%3}, [%4];"  \
                 : "=r"(r0), "=r"(r1), "=r"(r2), "=r"(r3) : "r"(addr))

DEVINL void mma16816(float* d, const uint32_t* a, const uint32_t* b) {
    asm volatile(
        "mma.sync.aligned.m16n8k16.row.col.f32.f16.f16.f32 "
        "{%0,%1,%2,%3}, {%4,%5,%6,%7}, {%8,%9}, {%0,%1,%2,%3};"
        : "+f"(d[0]), "+f"(d[1]), "+f"(d[2]), "+f"(d[3])
        : "r"(a[0]), "r"(a[1]), "r"(a[2]), "r"(a[3]), "r"(b[0]), "r"(b[1]));
}

// ---------------- prep (fused w + x): fp32 -> fp16 + inverse row L2 norm -------
__global__ void prep_kernel(const float* __restrict__ x, const float* __restrict__ w) {
    int grow = (blockIdx.x * blockDim.x + threadIdx.x) >> 5;
    int lane = threadIdx.x & 31;

    const float* src;
    __half* dsth;
    float* dstn;
    int row, valid;
    if (grow < C_PAD) {
        src = w; dsth = g_wh; dstn = g_sw; row = grow; valid = C_COLS;
    } else {
        src = x; dsth = g_xh; dstn = g_rx; row = grow - C_PAD; valid = B_ROWS;
        if (row >= B_ROWS) return;
    }

    uint2* drow = reinterpret_cast<uint2*>(dsth + (size_t)row * DIM);
    if (row < valid) {
        const float4* p = reinterpret_cast<const float4*>(src + (size_t)row * DIM);
        float4 v0 = p[lane];
        float4 v1 = p[lane + 32];
        float s = v0.x * v0.x + v0.y * v0.y + v0.z * v0.z + v0.w * v0.w
                + v1.x * v1.x + v1.y * v1.y + v1.z * v1.z + v1.w * v1.w;
#pragma unroll
        for (int o = 16; o; o >>= 1) s += __shfl_xor_sync(0xFFFFFFFFu, s, o);
        __half2 h0 = __floats2half2_rn(v0.x, v0.y);
        __half2 h1 = __floats2half2_rn(v0.z, v0.w);
        __half2 h2 = __floats2half2_rn(v1.x, v1.y);
        __half2 h3 = __floats2half2_rn(v1.z, v1.w);
        uint2 u0, u1;
        u0.x = *reinterpret_cast<uint32_t*>(&h0);
        u0.y = *reinterpret_cast<uint32_t*>(&h1);
        u1.x = *reinterpret_cast<uint32_t*>(&h2);
        u1.y = *reinterpret_cast<uint32_t*>(&h3);
        drow[lane]      = u0;
        drow[lane + 32] = u1;
        if (lane == 0) dstn[row] = rsqrtf(s);
    } else {
        uint2 z = {0u, 0u};
        drow[lane]      = z;
        drow[lane + 32] = z;
        if (lane == 0) dstn[row] = 0.0f;
    }
}

// ---------------- GEMM ----------------
DEVINL void load_chunk(uint32_t sA, uint32_t sB, int m0, int n0, int k0, int tid) {
    const __half* xa = g_xh + (size_t)m0 * DIM + k0;
    const __half* wb = g_wh + (size_t)n0 * DIM + k0;
#pragma unroll
    for (int i = 0; i < 4; i++) {                 // A: 128 rows x 8 x 16B
        int g = tid + i * 256;
        int row = g >> 3, c = g & 7;
        cp16(sA + sw128((uint32_t)(row * 128 + c * 16)), xa + row * DIM + c * 8);
    }
#pragma unroll
    for (int i = 0; i < 4; i++) {                 // B: 128 rows x 8 x 16B
        int g = tid + i * 256;
        int row = g >> 3, c = g & 7;
        cp16(sB + sw128((uint32_t)(row * 128 + c * 16)), wb + row * DIM + c * 8);
    }
}

__global__ __launch_bounds__(256, 2)
void gemm_kernel(float* __restrict__ out) {
    extern __shared__ char smem[];
    uint32_t s0 = smem_u32(smem);

    int tid  = threadIdx.x;
    int wid  = tid >> 5;
    int lane = tid & 31;
    int bid  = blockIdx.x;
    int m0 = (bid >> 3) * TILE_M;
    int n0 = (bid & 7) * TILE_N;

    // prologue: prefetch chunks 0,1 into buffers 0,1
    load_chunk(s0, s0 + STAGE_A, m0, n0, 0 * K_CHUNK, tid);
    cp_commit();
    load_chunk(s0 + STAGE_BYTES, s0 + STAGE_BYTES + STAGE_A, m0, n0, 1 * K_CHUNK, tid);
    cp_commit();

    float acc[4][4][4];
#pragma unroll
    for (int i = 0; i < 4; i++)
#pragma unroll
        for (int j = 0; j < 4; j++)
#pragma unroll
            for (int k = 0; k < 4; k++) acc[i][j][k] = 0.0f;

    int warp_m = wid >> 2;       // 0..1  -> 64 rows
    int warp_n = wid & 3;        // 0..3  -> 32 cols

    int a_row  = warp_m * 64 + (lane & 15);
    int a_kadd = (lane & 16) >> 1;               // 0 or 8
    int b_row  = warp_n * 32 + (lane & 7) + ((lane & 16) >> 1);
    int b_kadd = lane & 8;                       // 0 or 8

#pragma unroll
    for (int c = 0; c < N_CHUNKS; c++) {
        if (c < N_CHUNKS - 1) cp_wait<1>();
        else                  cp_wait<0>();
        __syncthreads();

        // prefetch chunk c+2 into buffer (c+2)%3 == (c-1)%3, freed by the sync above
        if (c + 2 < N_CHUNKS) {
            uint32_t sp = s0 + ((c + 2) % N_STAGES) * STAGE_BYTES;
            load_chunk(sp, sp + STAGE_A, m0, n0, (c + 2) * K_CHUNK, tid);
            cp_commit();
        }

        uint32_t sA = s0 + (c % N_STAGES) * STAGE_BYTES;
        uint32_t sB = sA + STAGE_A;
#pragma unroll
        for (int ks = 0; ks < 4; ks++) {
            uint32_t a[4][4];
#pragma unroll
            for (int bm = 0; bm < 4; bm++) {
                int row  = a_row + bm * 16;
                int kcol = ks * 16 + a_kadd;
                LDSM_X4(a[bm][0], a[bm][1], a[bm][2], a[bm][3],
                        sA + sw128((uint32_t)(row * 128 + kcol * 2)));
            }
            uint32_t b[2][4];
#pragma unroll
            for (int bb = 0; bb < 2; bb++) {
                int row  = b_row + bb * 16;
                int kcol = ks * 16 + b_kadd;
                LDSM_X4(b[bb][0], b[bb][1], b[bb][2], b[bb][3],
                        sB + sw128((uint32_t)(row * 128 + kcol * 2)));
            }
#pragma unroll
            for (int bm = 0; bm < 4; bm++)
#pragma unroll
                for (int bb = 0; bb < 2; bb++) {
                    mma16816(acc[bm][2 * bb],     a[bm], &b[bb][0]);
                    mma16816(acc[bm][2 * bb + 1], a[bm], &b[bb][2]);
                }
        }
    }

    // ---------------- epilogue ----------------
#pragma unroll
    for (int bm = 0; bm < 4; bm++) {
        int ma = m0 + warp_m * 64 + bm * 16 + (lane >> 2);
        int mb = ma + 8;
        float ra = 2.0f * g_rx[ma];
        float rb = 2.0f * g_rx[mb];
        float* rowa = out + (size_t)ma * C_COLS;
        float* rowb = out + (size_t)mb * C_COLS;
#pragma unroll
        for (int bn = 0; bn < 4; bn++) {
            int col = n0 + warp_n * 32 + bn * 8 + (lane & 3) * 2;
            if (col < C_COLS) {
                float sc0 = g_sw[col];
                float sc1 = g_sw[col + 1];
                float2 va, vb;
                va.x = fminf(fmaf(ra * sc0, acc[bm][bn][0], -2.0f), 0.0f);
                va.y = fminf(fmaf(ra * sc1, acc[bm][bn][1], -2.0f), 0.0f);
                vb.x = fminf(fmaf(rb * sc0, acc[bm][bn][2], -2.0f), 0.0f);
                vb.y = fminf(fmaf(rb * sc1, acc[bm][bn][3], -2.0f), 0.0f);
                *reinterpret_cast<float2*>(rowa + col) = va;
                *reinterpret_cast<float2*>(rowb + col) = vb;
            }
        }
    }
}

// ---------------- launch ----------------
extern "C" void kernel_launch(void* const* d_in, const int* in_sizes, int n_in,
                              void* d_out, int out_size) {
    const float* x = (const float*)d_in[0];
    const float* w = (const float*)d_in[1];
    float* out = (float*)d_out;

    cudaFuncSetAttribute(gemm_kernel, cudaFuncAttributeMaxDynamicSharedMemorySize, SMEM_REQ);

    // fused prep: first C_PAD rows -> w, rest -> x
    prep_kernel<<<(C_PAD + B_ROWS) / 8, 256>>>(x, w);

    // GEMM: 1024 m-tiles x 8 n-tiles; n fastest for x L2 reuse
    gemm_kernel<<<(B_ROWS / TILE_M) * 8, 256, SMEM_REQ>>>(out);

    // weight passthrough (second output)
    long long logits_elems = (long long)B_ROWS * C_COLS;
    if ((long long)out_size >= logits_elems + (long long)C_COLS * DIM) {
        cudaMemcpyAsync(out + logits_elems, w, (size_t)C_COLS * DIM * sizeof(float),
                        cudaMemcpyDeviceToDevice);
    }
}